// round 4
// baseline (speedup 1.0000x reference)
#include <cuda_runtime.h>

#define B_    4
#define NH_   4
#define N_    1000
#define NF_   256
#define K_TOP 10
#define NODES (B_*N_)      // 4000
#define EDGES (B_*K_TOP*N_) // 40000
#define NB    128          // persistent blocks
#define NT    256          // threads per block

// ---- scratch layout (floats) ----
#define OFF_SCUR 0
#define OFF_ACUR (OFF_SCUR + NODES*3)
#define OFF_PEIN (OFF_ACUR + NODES)
#define OFF_FLAG (OFF_PEIN + NODES*16)
#define OFF_REIN (OFF_FLAG + EDGES)
#define OFF_BUFA (OFF_REIN + EDGES*5)
#define OFF_BUFB (OFF_BUFA + EDGES*NF_)
#define OFF_BASE (OFF_BUFB + EDGES*NF_)
#define OFF_PEH  (OFF_BASE + EDGES*NF_)
#define OFF_PE   (OFF_PEH  + NODES*NF_)
#define OFF_G2   (OFF_PE   + NODES*NF_)
#define OFF_G3   (OFF_G2   + NODES*NF_)
#define OFF_AGG  (OFF_G3   + NODES*NF_)
#define OFF_PPC  (OFF_AGG  + NODES*NF_)
#define SCRATCH_TOTAL (OFF_PPC + NODES*NF_)

__device__ float g_scratch[SCRATCH_TOTAL];
__device__ int   g_send[EDGES];
__device__ int   g_sendc[EDGES];
__device__ int   g_offsets[NODES+1];
__device__ int   g_Mact[1];
__device__ unsigned g_count;
__device__ unsigned g_gen;

__device__ __forceinline__ unsigned f2tf(float x) {
    unsigned r;
    asm("cvt.rna.tf32.f32 %0, %1;" : "=r"(r) : "f"(x));
    return r;
}

// ---------------------------------------------------------------------------
// shared memory union for the persistent kernel
// ---------------------------------------------------------------------------
#define SA 20
#define SB 136
struct TCSmem { unsigned As[2][128*SA]; unsigned Bs[2][16*SB]; };   // ~37.9KB
struct G64Smem { float As[16][68]; float Bs[16][68]; };
struct ScanSmem { int part[NT]; };
union SU {
    TCSmem tc;
    G64Smem g64;
    ScanSmem sc;
};

// ---------------------------------------------------------------------------
// grid barrier (sense via monotonically increasing generation counter)
// ---------------------------------------------------------------------------
__device__ __forceinline__ void gbar(unsigned& mygen) {
    __threadfence();                 // my stores -> L2 visible device-wide
    __syncthreads();
    if (threadIdx.x == 0) {
        unsigned arrived = atomicAdd(&g_count, 1u);
        if (arrived == NB - 1) {
            g_count = 0;
            __threadfence();
            atomicAdd(&g_gen, 1u);
        } else {
            while (atomicAdd(&g_gen, 0u) <= mygen) __nanosleep(64);
        }
    }
    __syncthreads();
    mygen++;
    __threadfence();                 // CCTL.IVALL: invalidate L1, fresh loads
    __syncthreads();
}

// ---------------------------------------------------------------------------
// prep: s_cur, a_cur, pe_in, out init, barrier reset
// ---------------------------------------------------------------------------
__global__ void prep_kernel(const float* __restrict__ a_hist,
                            const float* __restrict__ s_hist,
                            const float* __restrict__ s_delta,
                            const float* __restrict__ pr_b1,
                            float* __restrict__ scur, float* __restrict__ acur,
                            float* __restrict__ pein, float* __restrict__ out)
{
    if (blockIdx.x == 0 && threadIdx.x == 0) { g_count = 0; g_gen = 0; }
    int idx = blockIdx.x * blockDim.x + threadIdx.x;
    if (idx >= NODES) return;
    int b = idx / N_, n = idx % N_;
    acur[idx] = a_hist[(b*NH_ + NH_-1)*N_ + n];
    const float* sh = s_hist + ((size_t)(b*NH_ + NH_-1)*N_ + n)*3;
    float s0=sh[0], s1=sh[1], s2=sh[2];
    scur[idx*3+0]=s0; scur[idx*3+1]=s1; scur[idx*3+2]=s2;
    out[idx*3+0] = s0 + pr_b1[0];
    out[idx*3+1] = s1 + pr_b1[1];
    out[idx*3+2] = s2 + pr_b1[2];
    float* pp = pein + (size_t)idx*16;
#pragma unroll
    for (int h=0; h<NH_; ++h) {
        const float* sd = s_delta + ((size_t)(b*NH_+h)*N_ + n)*3;
        pp[h*3+0]=sd[0]; pp[h*3+1]=sd[1]; pp[h*3+2]=sd[2];
        pp[12+h] = a_hist[(b*NH_+h)*N_ + n];
    }
}

// ---------------------------------------------------------------------------
// top-10 nearest: j-loop split 2-way + stable merge
// ---------------------------------------------------------------------------
__global__ void __launch_bounds__(256)
topk_kernel(const float* __restrict__ scur, const float* __restrict__ acur,
            int* __restrict__ send, float* __restrict__ flag)
{
    __shared__ float sx[N_], sy[N_], sz[N_];
    __shared__ unsigned char st[N_];
    __shared__ float md[256][K_TOP];
    __shared__ short mi[256][K_TOP];
    int b = blockIdx.y;
    int tid = threadIdx.x;
    for (int j = tid; j < N_; j += 256) {
        int g = b*N_+j;
        sx[j]=scur[g*3+0]; sy[j]=scur[g*3+1]; sz[j]=scur[g*3+2];
        st[j] = acur[g] > 0.5f ? 1 : 0;
    }
    __syncthreads();
    int li = tid & 127;
    int half = tid >> 7;
    int i = blockIdx.x*128 + li;
    float dv[K_TOP]; short iv[K_TOP];
#pragma unroll
    for (int t=0;t<K_TOP;++t){ dv[t]=3.0e38f; iv[t]=0; }
    if (i < N_) {
        bool ti = st[i] != 0;
        float xi=sx[i], yi=sy[i], zi=sz[i];
        int j0 = half*500, j1 = j0+500;
        for (int j=j0;j<j1;++j) {
            float dx=__fadd_rn(xi,-sx[j]), dy=__fadd_rn(yi,-sy[j]), dz=__fadd_rn(zi,-sz[j]);
            float d = __fadd_rn(__fadd_rn(__fmul_rn(dx,dx),__fmul_rn(dy,dy)),__fmul_rn(dz,dz));
            if (ti && st[j]) d = 1e10f;
            if (d < dv[K_TOP-1]) {
#pragma unroll
                for (int t=K_TOP-1; t>=1; --t) {
                    if (d < dv[t-1])      { dv[t]=dv[t-1]; iv[t]=iv[t-1]; }
                    else if (d < dv[t])   { dv[t]=d;       iv[t]=(short)j; }
                }
                if (d < dv[0]) { dv[0]=d; iv[0]=(short)j; }
            }
        }
    }
#pragma unroll
    for (int t=0;t<K_TOP;++t){ md[tid][t]=dv[t]; mi[tid][t]=iv[t]; }
    __syncthreads();
    if (half == 0 && i < N_) {
        bool ti = st[i] != 0;
        int ia=0, ib=0;
        int gi = b*N_ + i;
#pragma unroll
        for (int t=0;t<K_TOP;++t) {
            float da = md[li][ia],     db = md[li+128][ib];
            float d; int j;
            if (da <= db) { d=da; j=mi[li][ia]; ia++; }
            else          { d=db; j=mi[li+128][ib]; ib++; }
            int rg = gi*K_TOP + t;
            send[rg] = b*N_ + j;
            flag[rg] = (!ti && d < 0.25f) ? 1.0f : 0.0f;
        }
    }
}

// ---------------------------------------------------------------------------
// tf32 tensor-core GEMM tile (128x128, BK=16, 8 warps)
// ---------------------------------------------------------------------------
__device__ void gemm_tc_tile(
    TCSmem& sm,
    const float* __restrict__ A, int lda,
    const float* __restrict__ W, int ldw,
    const float* __restrict__ bias,
    const float* __restrict__ add0, const float* __restrict__ add1,
    float* __restrict__ C, int ldc,
    int M, int K, int bm, int bn, int relu,
    int out_mode, const float* __restrict__ w1, float* __restrict__ outp)
{
    int tid = threadIdx.x;
    int wid = tid >> 5, lane = tid & 31;
    int gid = lane >> 2, tig = lane & 3;
    int warp_m = (wid & 3) * 32;
    int warp_n = (wid >> 2) * 64;

    float acc[2][8][4];
#pragma unroll
    for (int f=0;f<2;++f)
#pragma unroll
        for (int g=0;g<8;++g)
#pragma unroll
            for (int q=0;q<4;++q) acc[f][g][q]=0.f;

    int nk = K / 16;

#define TC_LOAD(buf, k0)                                                      \
    {                                                                         \
        _Pragma("unroll")                                                     \
        for (int i = 0; i < 2; ++i) {                                         \
            int idx = tid + i * 256;                                          \
            int row = idx >> 2, kq = (idx & 3) * 4;                           \
            int gm = bm + row;                                                \
            float4 v = make_float4(0.f,0.f,0.f,0.f);                          \
            if (gm < M) v = *(const float4*)(A + (size_t)gm * lda + (k0) + kq);\
            sm.As[buf][row*SA + kq + 0] = f2tf(v.x);                          \
            sm.As[buf][row*SA + kq + 1] = f2tf(v.y);                          \
            sm.As[buf][row*SA + kq + 2] = f2tf(v.z);                          \
            sm.As[buf][row*SA + kq + 3] = f2tf(v.w);                          \
        }                                                                     \
        _Pragma("unroll")                                                     \
        for (int i = 0; i < 2; ++i) {                                         \
            int idx = tid + i * 256;                                          \
            int kk = idx >> 5, nn = (idx & 31) * 4;                           \
            float4 v = *(const float4*)(W + (size_t)((k0)+kk) * ldw + bn + nn);\
            sm.Bs[buf][kk*SB + nn + 0] = f2tf(v.x);                           \
            sm.Bs[buf][kk*SB + nn + 1] = f2tf(v.y);                           \
            sm.Bs[buf][kk*SB + nn + 2] = f2tf(v.z);                           \
            sm.Bs[buf][kk*SB + nn + 3] = f2tf(v.w);                           \
        }                                                                     \
    }

    __syncthreads();
    TC_LOAD(0, 0);
    __syncthreads();

    for (int t = 0; t < nk; ++t) {
        int cur = t & 1, nxt = cur ^ 1;
        if (t + 1 < nk) TC_LOAD(nxt, (t + 1) * 16);
#pragma unroll
        for (int ks = 0; ks < 2; ++ks) {
            int kb = ks * 8;
            unsigned a[2][4], bfr[8][2];
#pragma unroll
            for (int f = 0; f < 2; ++f) {
                int rb = warp_m + f*16;
                a[f][0] = sm.As[cur][(rb+gid  )*SA + kb + tig];
                a[f][1] = sm.As[cur][(rb+gid+8)*SA + kb + tig];
                a[f][2] = sm.As[cur][(rb+gid  )*SA + kb + tig + 4];
                a[f][3] = sm.As[cur][(rb+gid+8)*SA + kb + tig + 4];
            }
#pragma unroll
            for (int g = 0; g < 8; ++g) {
                int nb = warp_n + g*8;
                bfr[g][0] = sm.Bs[cur][(kb+tig  )*SB + nb + gid];
                bfr[g][1] = sm.Bs[cur][(kb+tig+4)*SB + nb + gid];
            }
#pragma unroll
            for (int f = 0; f < 2; ++f)
#pragma unroll
                for (int g = 0; g < 8; ++g) {
                    asm volatile(
                        "mma.sync.aligned.m16n8k8.row.col.f32.tf32.tf32.f32 "
                        "{%0,%1,%2,%3},{%4,%5,%6,%7},{%8,%9},{%0,%1,%2,%3};"
                        : "+f"(acc[f][g][0]), "+f"(acc[f][g][1]),
                          "+f"(acc[f][g][2]), "+f"(acc[f][g][3])
                        : "r"(a[f][0]), "r"(a[f][1]), "r"(a[f][2]), "r"(a[f][3]),
                          "r"(bfr[g][0]), "r"(bfr[g][1]));
                }
        }
        __syncthreads();
    }
#undef TC_LOAD

    if (!out_mode) {
#pragma unroll
        for (int f = 0; f < 2; ++f) {
            int r0 = bm + warp_m + f*16 + gid;
            int r1 = r0 + 8;
#pragma unroll
            for (int g = 0; g < 8; ++g) {
                int ccol = bn + warp_n + g*8 + tig*2;
                float b0 = bias ? bias[ccol] : 0.f;
                float b1 = bias ? bias[ccol+1] : 0.f;
                if (r0 < M) {
                    size_t off = (size_t)r0 * ldc + ccol;
                    float v0 = acc[f][g][0] + b0;
                    float v1 = acc[f][g][1] + b1;
                    if (add0) { v0 += add0[off]; v1 += add0[off+1]; }
                    if (add1) { v0 += add1[off]; v1 += add1[off+1]; }
                    if (relu) { v0 = fmaxf(v0,0.f); v1 = fmaxf(v1,0.f); }
                    *(float2*)(C + off) = make_float2(v0, v1);
                }
                if (r1 < M) {
                    size_t off = (size_t)r1 * ldc + ccol;
                    float v0 = acc[f][g][2] + b0;
                    float v1 = acc[f][g][3] + b1;
                    if (add0) { v0 += add0[off]; v1 += add0[off+1]; }
                    if (add1) { v0 += add1[off]; v1 += add1[off+1]; }
                    if (relu) { v0 = fmaxf(v0,0.f); v1 = fmaxf(v1,0.f); }
                    *(float2*)(C + off) = make_float2(v0, v1);
                }
            }
        }
    } else {
        // hout = relu(acc + bias); out[r] += hout-slice @ w1 (256x3)
#pragma unroll
        for (int f = 0; f < 2; ++f) {
            int r0 = bm + warp_m + f*16 + gid;
            int r1 = r0 + 8;
            float p0[3] = {0.f,0.f,0.f};
            float p1[3] = {0.f,0.f,0.f};
#pragma unroll
            for (int g = 0; g < 8; ++g) {
                int ccol = bn + warp_n + g*8 + tig*2;
#pragma unroll
                for (int c = 0; c < 2; ++c) {
                    int col = ccol + c;
                    float w0 = __ldg(w1 + col*3 + 0);
                    float w1v= __ldg(w1 + col*3 + 1);
                    float w2 = __ldg(w1 + col*3 + 2);
                    float bb = bias ? bias[col] : 0.f;
                    float v0 = fmaxf(acc[f][g][0+c] + bb, 0.f);
                    float v1 = fmaxf(acc[f][g][2+c] + bb, 0.f);
                    p0[0]=fmaf(v0,w0,p0[0]); p0[1]=fmaf(v0,w1v,p0[1]); p0[2]=fmaf(v0,w2,p0[2]);
                    p1[0]=fmaf(v1,w0,p1[0]); p1[1]=fmaf(v1,w1v,p1[1]); p1[2]=fmaf(v1,w2,p1[2]);
                }
            }
            // reduce across the 4 tig lanes (consecutive lane ids)
#pragma unroll
            for (int j = 0; j < 3; ++j) {
                p0[j] += __shfl_xor_sync(0xffffffffu, p0[j], 1);
                p0[j] += __shfl_xor_sync(0xffffffffu, p0[j], 2);
                p1[j] += __shfl_xor_sync(0xffffffffu, p1[j], 1);
                p1[j] += __shfl_xor_sync(0xffffffffu, p1[j], 2);
            }
            if (tig == 0) {
                if (r0 < M) {
                    atomicAdd(outp + r0*3 + 0, p0[0]);
                    atomicAdd(outp + r0*3 + 1, p0[1]);
                    atomicAdd(outp + r0*3 + 2, p0[2]);
                }
                if (r1 < M) {
                    atomicAdd(outp + r1*3 + 0, p1[0]);
                    atomicAdd(outp + r1*3 + 1, p1[1]);
                    atomicAdd(outp + r1*3 + 2, p1[2]);
                }
            }
        }
    }
}

// ---------------------------------------------------------------------------
// fp32 64x64 tile for small-K layers (K<=16)
// ---------------------------------------------------------------------------
__device__ void gemm64_tile(
    G64Smem& sm,
    const float* __restrict__ A, int lda,
    const float* __restrict__ W, const float* __restrict__ bias,
    float* __restrict__ C, int M, int K, int NOUT, int relu,
    int bm, int bn)
{
    int tid = threadIdx.x;
    int ty = tid >> 4, tx = tid & 15;
    int la_row = tid >> 2;
    int la_k0  = (tid & 3) * 4;

    __syncthreads();
    {
        int gm = bm + la_row;
#pragma unroll
        for (int q = 0; q < 4; ++q) {
            int kk = la_k0 + q;
            sm.As[kk][la_row] = (gm < M && kk < K) ? A[(size_t)gm * lda + kk] : 0.f;
        }
#pragma unroll
        for (int q = 0; q < 4; ++q) {
            int lin = tid + q * 256;
            int kk = lin >> 6;
            int nn = lin & 63;
            sm.Bs[kk][nn] = (kk < K) ? W[(size_t)kk * NOUT + bn + nn] : 0.f;
        }
    }
    __syncthreads();
    float acc[4][4] = {};
#pragma unroll
    for (int kk = 0; kk < 16; ++kk) {
        float av[4], bv[4];
#pragma unroll
        for (int q=0;q<4;++q) av[q] = sm.As[kk][ty*4+q];
#pragma unroll
        for (int q=0;q<4;++q) bv[q] = sm.Bs[kk][tx*4+q];
#pragma unroll
        for (int i=0;i<4;++i)
#pragma unroll
            for (int j=0;j<4;++j)
                acc[i][j] = fmaf(av[i], bv[j], acc[i][j]);
    }
#pragma unroll
    for (int i=0;i<4;++i) {
        int gm = bm + ty*4 + i;
        if (gm >= M) continue;
#pragma unroll
        for (int j=0;j<4;++j) {
            int gn = bn + tx*4 + j;
            float v = acc[i][j] + bias[gn];
            if (relu) v = fmaxf(v, 0.f);
            C[(size_t)gm * NOUT + gn] = v;
        }
    }
}

// ---------------------------------------------------------------------------
// the persistent mega-kernel: everything after prep/topk
// ---------------------------------------------------------------------------
__global__ void __launch_bounds__(NT)
mega_kernel(const float* __restrict__ pe_w0, const float* __restrict__ pe_b0,
            const float* __restrict__ pe_w1, const float* __restrict__ pe_b1,
            const float* __restrict__ re_w0, const float* __restrict__ re_b0,
            const float* __restrict__ re_w1, const float* __restrict__ re_b1,
            const float* __restrict__ re_w2, const float* __restrict__ re_b2,
            const float* __restrict__ rp_w,  const float* __restrict__ rp_b,
            const float* __restrict__ pp_w,  const float* __restrict__ pp_b,
            const float* __restrict__ pr_w0, const float* __restrict__ pr_b0,
            const float* __restrict__ pr_w1, float* __restrict__ out)
{
    __shared__ SU su;
    unsigned gen = 0;
    const int bx = blockIdx.x;
    const int tid = threadIdx.x;

    float* S = g_scratch;
    float* scur=S+OFF_SCUR; float* acur=S+OFF_ACUR; float* pein=S+OFF_PEIN;
    float* flag=S+OFF_FLAG; float* rein=S+OFF_REIN;
    float* bufA=S+OFF_BUFA; float* bufB=S+OFF_BUFB; float* base=S+OFF_BASE;
    float* peh =S+OFF_PEH;  float* pe  =S+OFF_PE;   float* G2  =S+OFF_G2;
    float* G3  =S+OFF_G3;   float* agg =S+OFF_AGG;  float* ppc =S+OFF_PPC;

    // ---- Phase A: scan (block 0) ----
    if (bx == 0) {
        int local[16];
        int run = 0;
#pragma unroll
        for (int q=0;q<16;++q) {
            int node = tid*16+q;
            int c = 0;
            if (node < NODES) {
#pragma unroll
                for (int k=0;k<K_TOP;++k) c += (flag[node*K_TOP+k] != 0.f);
            }
            local[q]=run; run+=c;
        }
        su.sc.part[tid]=run;
        __syncthreads();
        for (int d=1; d<NT; d<<=1) {
            int v = (tid>=d) ? su.sc.part[tid-d] : 0;
            __syncthreads();
            su.sc.part[tid] += v;
            __syncthreads();
        }
        int before = (tid==0) ? 0 : su.sc.part[tid-1];
#pragma unroll
        for (int q=0;q<16;++q) {
            int node = tid*16+q;
            if (node < NODES) g_offsets[node] = before + local[q];
        }
        if (tid == NT-1) { g_offsets[NODES] = su.sc.part[NT-1]; g_Mact[0] = su.sc.part[NT-1]; }
    }
    gbar(gen);

    // ---- Phase B: fill (per-edge) + peh gemm (fp32, K=16) ----
    for (int r = bx*NT + tid; r < EDGES; r += NB*NT) {
        float f = flag[r];
        if (f != 0.f) {
            int node = r / K_TOP, k = r % K_TOP;
            int rank = 0;
            for (int kk = 0; kk < k; ++kk) rank += (flag[node*K_TOP+kk] != 0.f);
            int pos = g_offsets[node] + rank;
            int s = g_send[r];
            g_sendc[pos] = s;
            float* o = rein + (size_t)pos*5;
            o[0] = acur[node];
            o[1] = acur[s];
            o[2] = scur[node*3+0] - scur[s*3+0];
            o[3] = scur[node*3+1] - scur[s*3+1];
            o[4] = scur[node*3+2] - scur[s*3+2];
        }
    }
    {
        int nt = ((NODES+63)>>6) * 4;   // 63*4
        for (int t = bx; t < nt; t += NB)
            gemm64_tile(su.g64, pein, 16, pe_w0, pe_b0, peh, NODES, 16, NF_, 1,
                        (t>>2)*64, (t&3)*64);
    }
    gbar(gen);

    int Ma = *(volatile int*)g_Mact;
    int ntE = ((Ma+127)>>7) * 2;

    // ---- Phase C: rein gemm (fp32, K=5) + pe TCN ----
    {
        int nt = ((Ma+63)>>6) * 4;
        for (int t = bx; t < nt; t += NB)
            gemm64_tile(su.g64, rein, 5, re_w0, re_b0, bufA, Ma, 5, NF_, 1,
                        (t>>2)*64, (t&3)*64);
        for (int t = bx; t < 64; t += NB)
            gemm_tc_tile(su.tc, peh, NF_, pe_w1, NF_, pe_b1, 0, 0, pe, NF_,
                         NODES, NF_, (t>>1)*128, (t&1)*128, 1, 0, 0, 0);
    }
    gbar(gen);

    // ---- Phase D: TCE1 + ppc ----
    for (int t = bx; t < ntE; t += NB)
        gemm_tc_tile(su.tc, bufA, NF_, re_w1, NF_, re_b1, 0, 0, bufB, NF_,
                     Ma, NF_, (t>>1)*128, (t&1)*128, 1, 0, 0, 0);
    for (int t = bx; t < 64; t += NB)
        gemm_tc_tile(su.tc, pe, NF_, pp_w, NF_, pp_b, 0, 0, ppc, NF_,
                     NODES, NF_, (t>>1)*128, (t&1)*128, 0, 0, 0, 0);
    gbar(gen);

    // ---- Phase E: TCE2 ----
    for (int t = bx; t < ntE; t += NB)
        gemm_tc_tile(su.tc, bufB, NF_, re_w2, NF_, re_b2, 0, 0, bufA, NF_,
                     Ma, NF_, (t>>1)*128, (t&1)*128, 1, 0, 0, 0);
    gbar(gen);

    // ---- Phase F: base ----
    for (int t = bx; t < ntE; t += NB)
        gemm_tc_tile(su.tc, bufA, NF_, rp_w, NF_, rp_b, 0, 0, base, NF_,
                     Ma, NF_, (t>>1)*128, (t&1)*128, 0, 0, 0, 0);
    gbar(gen);

    // ---- propagation steps ----
    for (int step = 0; step < 3; ++step) {
        // G2 = pe @ rp_w[256:512], G3 = pe @ rp_w[512:768]
        for (int t = bx; t < 128; t += NB) {
            int which = t >> 6;        // 0: G2, 1: G3
            int tt = t & 63;
            gemm_tc_tile(su.tc, pe, NF_,
                         rp_w + (which ? 512 : 256)*NF_, NF_, 0, 0, 0,
                         which ? G3 : G2, NF_,
                         NODES, NF_, (tt>>1)*128, (tt&1)*128, 0, 0, 0, 0);
        }
        gbar(gen);
        // agg
        for (int w = bx*NT + tid; w < NODES*64; w += NB*NT) {
            int node = w >> 6, q = (w & 63) * 4;
            float4 g2 = *(const float4*)(G2 + (size_t)node*NF_ + q);
            int e0 = g_offsets[node], e1 = g_offsets[node+1];
            float4 a = make_float4(0.f,0.f,0.f,0.f);
            for (int e = e0; e < e1; ++e) {
                float4 bs = *(const float4*)(base + (size_t)e*NF_ + q);
                float4 g3 = *(const float4*)(G3 + (size_t)g_sendc[e]*NF_ + q);
                a.x += fmaxf(bs.x + g2.x + g3.x, 0.f);
                a.y += fmaxf(bs.y + g2.y + g3.y, 0.f);
                a.z += fmaxf(bs.z + g2.z + g3.z, 0.f);
                a.w += fmaxf(bs.w + g2.w + g3.w, 0.f);
            }
            *(float4*)(agg + (size_t)node*NF_ + q) = a;
        }
        gbar(gen);
        // pe = relu(ppc + agg @ pp_w[256:512] + pe)
        for (int t = bx; t < 64; t += NB)
            gemm_tc_tile(su.tc, agg, NF_, pp_w + 256*NF_, NF_, 0, ppc, pe, pe, NF_,
                         NODES, NF_, (t>>1)*128, (t&1)*128, 1, 0, 0, 0);
        gbar(gen);
    }

    // ---- final: pr GEMM with fused out ----
    for (int t = bx; t < 64; t += NB)
        gemm_tc_tile(su.tc, pe, NF_, pr_w0, NF_, pr_b0, 0, 0, 0, 0,
                     NODES, NF_, (t>>1)*128, (t&1)*128, 1, 1, pr_w1, out);
}

// ---------------------------------------------------------------------------
extern "C" void kernel_launch(void* const* d_in, const int* in_sizes, int n_in,
                              void* d_out, int out_size)
{
    const float* a_hist =(const float*)d_in[0];
    const float* s_hist =(const float*)d_in[1];
    const float* s_delta=(const float*)d_in[2];
    const float* pe_w0=(const float*)d_in[3];  const float* pe_b0=(const float*)d_in[4];
    const float* pe_w1=(const float*)d_in[5];  const float* pe_b1=(const float*)d_in[6];
    const float* re_w0=(const float*)d_in[7];  const float* re_b0=(const float*)d_in[8];
    const float* re_w1=(const float*)d_in[9];  const float* re_b1=(const float*)d_in[10];
    const float* re_w2=(const float*)d_in[11]; const float* re_b2=(const float*)d_in[12];
    const float* rp_w =(const float*)d_in[13]; const float* rp_b =(const float*)d_in[14];
    const float* pp_w =(const float*)d_in[15]; const float* pp_b =(const float*)d_in[16];
    const float* pr_w0=(const float*)d_in[17]; const float* pr_b0=(const float*)d_in[18];
    const float* pr_w1=(const float*)d_in[19]; const float* pr_b1=(const float*)d_in[20];
    float* out = (float*)d_out;

    void* sp;   cudaGetSymbolAddress(&sp, g_scratch);
    void* p1;   cudaGetSymbolAddress(&p1, g_send);
    float* S = (float*)sp;
    int* send = (int*)p1;

    float* scur=S+OFF_SCUR; float* acur=S+OFF_ACUR; float* pein=S+OFF_PEIN;
    float* flag=S+OFF_FLAG;

    prep_kernel<<<(NODES+127)/128,128>>>(a_hist,s_hist,s_delta,pr_b1,scur,acur,pein,out);
    topk_kernel<<<dim3(8,B_),256>>>(scur,acur,send,flag);
    mega_kernel<<<NB,NT>>>(pe_w0,pe_b0,pe_w1,pe_b1,re_w0,re_b0,re_w1,re_b1,
                           re_w2,re_b2,rp_w,rp_b,pp_w,pp_b,pr_w0,pr_b0,pr_w1,out);
}